// round 13
// baseline (speedup 1.0000x reference)
#include <cuda_runtime.h>
#include <cuda_bf16.h>
#include <math_constants.h>

#define NMAX 100000
#define GMAX 64
#define SLOTS 64
#define EPS 1e-5f
#define NEG_SLOPE 0.2f
#define NBLK 592          // 148 SMs x 4 blocks, all co-resident
#define NTHR 256

// ---------------- scratch (device globals) ----------------
__device__ __align__(16) unsigned g_B128[NMAX * 64];  // bf16x2, 128 cols/node
__device__ __align__(16) unsigned g_B64a[NMAX * 32];  // bf16x2, up to 64 cols/node
__device__ __align__(16) unsigned g_B64b[NMAX * 32];
__device__ float g_dinv[NMAX];
__device__ int   g_deg[NMAX];
__device__ int   g_cursor[NMAX];
__device__ int   g_perm[NMAX * SLOTS];
__device__ __align__(16) float g_as[NMAX * 4];
__device__ __align__(16) float g_ad[NMAX * 4];
__device__ float g_pool[GMAX * 32];
__device__ float g_cnt[GMAX];
__device__ unsigned g_gmaxu[4];
__device__ unsigned g_gen  = 0;
__device__ unsigned g_bcnt = 0;

// ---------------- grid-wide barrier (volatile-load polling) ----------------
__device__ __forceinline__ void gridbar() {
    __syncthreads();
    if (threadIdx.x == 0) {
        unsigned my = *(volatile unsigned*)&g_gen;
        __threadfence();
        if (atomicAdd(&g_bcnt, 1u) == NBLK - 1u) {
            atomicExch(&g_bcnt, 0u);
            __threadfence();
            atomicAdd(&g_gen, 1u);
        } else {
            while (*(volatile unsigned*)&g_gen == my) __nanosleep(64);
        }
        __threadfence();
    }
    __syncthreads();
}

__device__ __forceinline__ float lrelu(float x) { return x > 0.f ? x : NEG_SLOPE * x; }
__device__ __forceinline__ float2 bf2f(unsigned u) {
    return __bfloat1622float2(*reinterpret_cast<const __nv_bfloat162*>(&u));
}
__device__ __forceinline__ unsigned f2bf(float a, float b) {
    __nv_bfloat162 p = __floats2bfloat162_rn(a, b);
    return *reinterpret_cast<unsigned*>(&p);
}
__device__ __forceinline__ unsigned f2tf(float f) {
    unsigned u;
    asm("cvt.rna.tf32.f32 %0, %1;" : "=r"(u) : "f"(f));
    return u;
}
__device__ __forceinline__ unsigned fenc(float f) {
    int b = __float_as_int(f);
    return (b >= 0) ? ((unsigned)b | 0x80000000u) : (unsigned)(~b);
}
__device__ __forceinline__ float fdec(unsigned k) {
    return (k & 0x80000000u) ? __int_as_float((int)(k & 0x7FFFFFFFu))
                             : __int_as_float((int)~k);
}

__shared__ __align__(16) float smw[10240];   // 40KB stage scratch

// ---------------- tensor-core MMA m16n8k8 tf32 -> fp32 ----------------
__device__ __forceinline__ void mma1688(float c[4], unsigned a0, unsigned a1,
                                        unsigned a2, unsigned a3, unsigned b0, unsigned b1) {
    asm volatile(
        "mma.sync.aligned.m16n8k8.row.col.f32.tf32.tf32.f32 "
        "{%0,%1,%2,%3}, {%4,%5,%6,%7}, {%8,%9}, {%0,%1,%2,%3};"
        : "+f"(c[0]), "+f"(c[1]), "+f"(c[2]), "+f"(c[3])
        : "r"(a0), "r"(a1), "r"(a2), "r"(a3), "r"(b0), "r"(b1));
}

// ---------------- GEMM via tf32 MMA: A bf16 -> C bf16, opt bias+BN+relu, opt row-scale ----------------
template <int KIN, int KOUT, bool EPI, bool RSC>
__device__ void stage_mma(const unsigned* __restrict__ Ab, unsigned* __restrict__ Cb,
                          const float* __restrict__ W, int n, int lane, int gw, int GW,
                          const float* __restrict__ bias, const float* __restrict__ gam,
                          const float* __restrict__ bet, const float* __restrict__ mu,
                          const float* __restrict__ var) {
    constexpr int KS = KIN / 8;
    constexpr int NT = KOUT / 8;
    constexpr int JT = (NT >= 8) ? 8 : NT;
    constexpr int CHUNKS = NT / JT;
    constexpr int KIN2 = KIN / 2;
    constexpr int KOUT2 = KOUT / 2;

    uint2* bsm = reinterpret_cast<uint2*>(smw);
    for (int i = threadIdx.x; i < NT * KS * 32; i += NTHR) {
        int j = i / (KS * 32);
        int rem = i - j * (KS * 32);
        int s = rem >> 5;
        int l = rem & 31;
        int c_ = l & 3, nn = 8 * j + (l >> 2);
        int k0 = 8 * s + c_;
        unsigned v0 = f2tf(__ldg(W + k0 * KOUT + nn));
        unsigned v1 = f2tf(__ldg(W + (k0 + 4) * KOUT + nn));
        bsm[i] = make_uint2(v0, v1);
    }
    float* epiA = smw + 8192;
    float* epiB = smw + 8192 + KOUT;
    if constexpr (EPI) {
        for (int cix = threadIdx.x; cix < KOUT; cix += NTHR) {
            float Av = __ldg(gam + cix) * rsqrtf(__ldg(var + cix) + EPS);
            epiA[cix] = Av;
            epiB[cix] = __ldg(bet + cix) + (__ldg(bias + cix) - __ldg(mu + cix)) * Av;
        }
    }
    __syncthreads();

    int nrt = (n + 15) >> 4;
    int c = lane & 3, q = lane >> 2;
    int hw = c >> 1;
    bool hi = (c & 1);
    for (int T = gw; T < nrt * CHUNKS; T += GW) {
        int rt = (CHUNKS == 1) ? T : (T / CHUNKS);
        int ch = (CHUNKS == 1) ? 0 : (T - rt * CHUNKS);
        int r0 = rt * 16 + q;
        int r1 = r0 + 8;
        int rA = r0 < n ? r0 : n - 1;
        int rB = r1 < n ? r1 : n - 1;
        const unsigned* arow0 = Ab + (size_t)rA * KIN2;
        const unsigned* arow1 = Ab + (size_t)rB * KIN2;
        float acc[JT][4];
#pragma unroll
        for (int jj = 0; jj < JT; jj++) {
            acc[jj][0] = 0.f; acc[jj][1] = 0.f; acc[jj][2] = 0.f; acc[jj][3] = 0.f;
        }
#pragma unroll
        for (int s = 0; s < KS; s++) {
            unsigned wa0 = __ldg(arow0 + 4 * s + hw);
            unsigned wa1 = __ldg(arow0 + 4 * s + 2 + hw);
            unsigned wb0 = __ldg(arow1 + 4 * s + hw);
            unsigned wb1 = __ldg(arow1 + 4 * s + 2 + hw);
            unsigned a0 = hi ? (wa0 & 0xFFFF0000u) : (wa0 << 16);
            unsigned a2 = hi ? (wa1 & 0xFFFF0000u) : (wa1 << 16);
            unsigned a1 = hi ? (wb0 & 0xFFFF0000u) : (wb0 << 16);
            unsigned a3 = hi ? (wb1 & 0xFFFF0000u) : (wb1 << 16);
#pragma unroll
            for (int jj = 0; jj < JT; jj++) {
                uint2 bb = bsm[((ch * JT + jj) * KS + s) * 32 + lane];
                mma1688(acc[jj], a0, a1, a2, a3, bb.x, bb.y);
            }
        }
        float dr0 = 1.f, dr1 = 1.f;
        if constexpr (RSC) {
            dr0 = __ldg(g_dinv + rA);
            dr1 = __ldg(g_dinv + rB);
        }
#pragma unroll
        for (int jj = 0; jj < JT; jj++) {
            int col0 = 8 * (ch * JT + jj) + 2 * c;
            float x0 = acc[jj][0], x1 = acc[jj][1], x2 = acc[jj][2], x3 = acc[jj][3];
            if constexpr (EPI) {
                float A0 = epiA[col0], B0 = epiB[col0];
                float A1 = epiA[col0 + 1], B1 = epiB[col0 + 1];
                x0 = fmaxf(x0 * A0 + B0, 0.f); x1 = fmaxf(x1 * A1 + B1, 0.f);
                x2 = fmaxf(x2 * A0 + B0, 0.f); x3 = fmaxf(x3 * A1 + B1, 0.f);
            }
            if constexpr (RSC) {
                x0 *= dr0; x1 *= dr0; x2 *= dr1; x3 *= dr1;
            }
            int ci = col0 >> 1;
            if (r0 < n) Cb[(size_t)r0 * KOUT2 + ci] = f2bf(x0, x1);
            if (r1 < n) Cb[(size_t)r1 * KOUT2 + ci] = f2bf(x2, x3);
        }
    }
}

// ---------------- GCN agg (D=64), PRESCALED: quad-edge (8 lanes x uint4 per 128B row) ----------------
// Items 0..cnt (item cnt = self). Subgroup q handles items q, q+4, ...
// BN epilogue constants staged in smem (smw[0..63]=A, smw[64..127]=B).
template <bool EPIL>
__device__ void stage_agg64(const unsigned* __restrict__ featb, unsigned* __restrict__ outb, int n,
                            int lane, int gw, int GW,
                            const float* __restrict__ bias, const float* __restrict__ gam,
                            const float* __restrict__ bet, const float* __restrict__ mu,
                            const float* __restrict__ var) {
    if constexpr (EPIL) {
        for (int cix = threadIdx.x; cix < 64; cix += NTHR) {
            float Av = __ldg(gam + cix) * rsqrtf(__ldg(var + cix) + EPS);
            smw[cix] = Av;
            smw[64 + cix] = __ldg(bet + cix) + (__ldg(bias + cix) - __ldg(mu + cix)) * Av;
        }
        __syncthreads();
    }
    const uint4* fb = reinterpret_cast<const uint4*>(featb);   // 8 uint4 per row
    uint4* ob = reinterpret_cast<uint4*>(outb);
    int q = lane >> 3;       // subgroup 0..3
    int li = lane & 7;       // uint4 index -> cols [8li, 8li+8)
    for (int w = gw; w < n; w += GW) {
        float di = g_dinv[w];
        int cnt = g_deg[w];
        const int* __restrict__ pl = g_perm + (size_t)w * SLOTS;
        int T = cnt + 1;
        float a[8];
#pragma unroll
        for (int j = 0; j < 8; j++) a[j] = 0.f;
        int e = q;
        for (; e + 4 < T; e += 8) {
            int i0 = e, i1 = e + 4;
            int s0 = (i0 < cnt) ? __ldg(pl + i0) : w;
            int s1 = (i1 < cnt) ? __ldg(pl + i1) : w;
            uint4 r0 = __ldg(fb + (size_t)s0 * 8 + li);
            uint4 r1 = __ldg(fb + (size_t)s1 * 8 + li);
            float2 p;
            p = bf2f(r0.x); a[0] += p.x; a[1] += p.y;
            p = bf2f(r0.y); a[2] += p.x; a[3] += p.y;
            p = bf2f(r0.z); a[4] += p.x; a[5] += p.y;
            p = bf2f(r0.w); a[6] += p.x; a[7] += p.y;
            p = bf2f(r1.x); a[0] += p.x; a[1] += p.y;
            p = bf2f(r1.y); a[2] += p.x; a[3] += p.y;
            p = bf2f(r1.z); a[4] += p.x; a[5] += p.y;
            p = bf2f(r1.w); a[6] += p.x; a[7] += p.y;
        }
        for (; e < T; e += 4) {
            int sn = (e < cnt) ? __ldg(pl + e) : w;
            uint4 r = __ldg(fb + (size_t)sn * 8 + li);
            float2 p;
            p = bf2f(r.x); a[0] += p.x; a[1] += p.y;
            p = bf2f(r.y); a[2] += p.x; a[3] += p.y;
            p = bf2f(r.z); a[4] += p.x; a[5] += p.y;
            p = bf2f(r.w); a[6] += p.x; a[7] += p.y;
        }
        __syncwarp();
#pragma unroll
        for (int j = 0; j < 8; j++) {
            a[j] += __shfl_xor_sync(0xffffffffu, a[j], 8);
            a[j] += __shfl_xor_sync(0xffffffffu, a[j], 16);
        }
        if (lane < 8) {
            float o[8];
            if constexpr (EPIL) {
#pragma unroll
                for (int j = 0; j < 8; j++) {
                    int cix = 8 * li + j;
                    o[j] = fmaxf(a[j] * (di * smw[cix]) + smw[64 + cix], 0.f);
                }
            } else {
#pragma unroll
                for (int j = 0; j < 8; j++) o[j] = a[j] * di;
            }
            ob[(size_t)w * 8 + li] = make_uint4(f2bf(o[0], o[1]), f2bf(o[2], o[3]),
                                                f2bf(o[4], o[5]), f2bf(o[6], o[7]));
        }
    }
}

// ---------------- GCN agg (D=32), PRESCALED, two nodes per warp, bf16 out + BN epilogue ----------------
__device__ void stage_agg32_dual(const unsigned* __restrict__ featb, unsigned* __restrict__ outb, int n,
                                 int lane, int gw, int GW,
                                 const float* __restrict__ bias, const float* __restrict__ gam,
                                 const float* __restrict__ bet, const float* __restrict__ mu,
                                 const float* __restrict__ var) {
    int sub = lane >> 4;
    int li = lane & 15;
    int d0 = 2 * li, d1 = 2 * li + 1;
    float A0 = __ldg(gam + d0) * rsqrtf(__ldg(var + d0) + EPS);
    float B0 = __ldg(bet + d0) + (__ldg(bias + d0) - __ldg(mu + d0)) * A0;
    float A1 = __ldg(gam + d1) * rsqrtf(__ldg(var + d1) + EPS);
    float B1 = __ldg(bet + d1) + (__ldg(bias + d1) - __ldg(mu + d1)) * A1;

    for (int base = gw * 2; base < n; base += GW * 2) {
        int w = base + sub;
        bool valid = w < n;
        int wc = valid ? w : n - 1;
        float di = g_dinv[wc];
        int cnt = g_deg[wc];
        int cnto = __shfl_xor_sync(0xffffffffu, cnt, 16);
        int cmax = cnt > cnto ? cnt : cnto;
        const int* __restrict__ pl = g_perm + (size_t)wc * SLOTS;
        float ax, ay;
        {
            float2 v = bf2f(__ldg(featb + (size_t)wc * 16 + li));
            ax = v.x; ay = v.y;
        }
        int e = 0;
        for (; e + 4 <= cmax; e += 4) {
            int s[4]; float g[4]; unsigned r[4];
#pragma unroll
            for (int u = 0; u < 4; u++) {
                bool a = (e + u) < cnt;
                s[u] = a ? __ldg(pl + e + u) : wc;
                g[u] = a ? 1.f : 0.f;
            }
#pragma unroll
            for (int u = 0; u < 4; u++) r[u] = __ldg(featb + (size_t)s[u] * 16 + li);
#pragma unroll
            for (int u = 0; u < 4; u++) {
                float2 v = bf2f(r[u]);
                ax += g[u] * v.x; ay += g[u] * v.y;
            }
        }
        for (; e < cmax; e++) {
            bool a = e < cnt;
            int sn = a ? __ldg(pl + e) : wc;
            float g = a ? 1.f : 0.f;
            float2 v = bf2f(__ldg(featb + (size_t)sn * 16 + li));
            ax += g * v.x; ay += g * v.y;
        }
        ax = fmaxf(ax * (di * A0) + B0, 0.f);
        ay = fmaxf(ay * (di * A1) + B1, 0.f);
        if (valid) outb[(size_t)w * 16 + li] = f2bf(ax, ay);
    }
}

// ---------------- the megakernel ----------------
__global__ void __launch_bounds__(NTHR, 4)
k_mega(const float* __restrict__ x, const int* __restrict__ src, const int* __restrict__ dst,
       const int* __restrict__ batch, int n, int E, int G,
       const float* W1, const float* b1, const float* g1, const float* be1, const float* m1, const float* v1,
       const float* W2, const float* b2, const float* g2, const float* be2, const float* m2, const float* v2,
       const float* W3, const float* b3, const float* g3, const float* be3, const float* m3, const float* v3,
       const float* Wg, const float* ags, const float* agd, const float* bg,
       const float* Wc1, const float* bc1, const float* Wc2, const float* bc2,
       float* __restrict__ out) {
    int tid = threadIdx.x;
    int lane = tid & 31;
    int gt = blockIdx.x * NTHR + tid;
    int gw = gt >> 5;
    const int GT = NBLK * NTHR;
    const int GW = GT / 32;

    // S0: zero cursors/pool/cnt/gmax
    for (int i = gt; i < n; i += GT) g_cursor[i] = 0;
    if (gt < GMAX * 32) g_pool[gt] = 0.f;
    if (gt < GMAX) g_cnt[gt] = 0.f;
    if (gt < 4) g_gmaxu[gt] = 0u;
    gridbar();

    // S1: bucket scatter by dst
    for (int e = gt; e < E; e += GT) {
        int d = dst[e];
        int slot = atomicAdd(&g_cursor[d], 1);
        if (slot < SLOTS) g_perm[(size_t)d * SLOTS + slot] = src[e];
    }
    gridbar();

    // S2: finalize degree/dinv + convert x -> prescaled bf16
    for (int i = gt; i < n; i += GT) {
        int c = g_cursor[i];
        if (c > SLOTS) c = SLOTS;
        g_deg[i] = c;
        g_dinv[i] = rsqrtf((float)(c + 1));
    }
    for (int i = gt; i < n * 32; i += GT) {
        int node = i >> 5;
        int c = g_cursor[node];
        if (c > SLOTS) c = SLOTS;
        float di = rsqrtf((float)(c + 1));
        g_B64a[i] = f2bf(di * __ldg(x + 2 * i), di * __ldg(x + 2 * i + 1));
    }
    gridbar();

    // S3: aggregate prescaled input (linearity), out = bf16(di*acc)
    stage_agg64<false>(g_B64a, g_B64b, n, lane, gw, GW, nullptr, nullptr, nullptr, nullptr, nullptr);
    gridbar();

    // S4: tf32 GEMM 64->128 + bias/BN/relu
    stage_mma<64, 128, true, false>(g_B64b, g_B128, W1, n, lane, gw, GW, b1, g1, be1, m1, v1);
    gridbar();

    // S5: tf32 GEMM 128->64, out prescaled by dinv
    stage_mma<128, 64, false, true>(g_B128, g_B64a, W2, n, lane, gw, GW, nullptr, nullptr, nullptr, nullptr, nullptr);
    gridbar();

    // S6: aggregate + bias/BN/relu (di folded into epilogue)
    stage_agg64<true>(g_B64a, g_B64b, n, lane, gw, GW, b2, g2, be2, m2, v2);
    gridbar();

    // S7: tf32 GEMM 64->32, out prescaled by dinv
    stage_mma<64, 32, false, true>(g_B64b, g_B64a, W3, n, lane, gw, GW, nullptr, nullptr, nullptr, nullptr, nullptr);
    gridbar();

    // S8: aggregate + bias/BN/relu (32-dim), two nodes/warp
    stage_agg32_dual(g_B64a, g_B64b, n, lane, gw, GW, b3, g3, be3, m3, v3);
    gridbar();

    // S9: tf32 GEMM 32->128 (GAT projection), unscaled bf16 out
    stage_mma<32, 128, false, false>(g_B64b, g_B128, Wg, n, lane, gw, GW, nullptr, nullptr, nullptr, nullptr, nullptr);
    gridbar();

    // S10: attention coefficients from bf16 hh + per-head global max
    {
        unsigned* gm = reinterpret_cast<unsigned*>(smw);
        if (tid < 4) gm[tid] = 0u;
        __syncthreads();
        const float4* ags4 = reinterpret_cast<const float4*>(ags);
        const float4* agd4 = reinterpret_cast<const float4*>(agd);
        float4 sg = __ldg(ags4 + lane);
        float4 dg = __ldg(agd4 + lane);
        const uint2* hb = reinterpret_cast<const uint2*>(g_B128);
        float smax = -CUDART_INF_F;
        for (int node = gw; node < n; node += GW) {
            uint2 w = __ldg(hb + (size_t)node * 32 + lane);
            float2 p0 = bf2f(w.x), p1 = bf2f(w.y);
            float s = p0.x * sg.x + p0.y * sg.y + p1.x * sg.z + p1.y * sg.w;
            float d = p0.x * dg.x + p0.y * dg.y + p1.x * dg.z + p1.y * dg.w;
#pragma unroll
            for (int off = 4; off; off >>= 1) {
                s += __shfl_xor_sync(0xffffffffu, s, off);
                d += __shfl_xor_sync(0xffffffffu, d, off);
            }
            if ((lane & 7) == 0) {
                int h = lane >> 3;
                g_as[node * 4 + h] = s;
                g_ad[node * 4 + h] = d;
            }
            smax = fmaxf(smax, s);
        }
        if ((lane & 7) == 0) atomicMax(&gm[lane >> 3], fenc(smax));
        __syncthreads();
        if (tid < 4) atomicMax(&g_gmaxu[tid], gm[tid]);
    }
    gridbar();

    // S11: GAT aggregation — dual-edge half-warp LDG.128 gathers + fused pool
    {
        const uint4* hb4 = reinterpret_cast<const uint4*>(g_B128);   // 16 uint4 per row
        int li = lane & 15;      // uint4 index -> cols [8li, 8li+8)
        int h = lane >> 4;       // half id: items h, h+2, ...
        int myh = li >> 2;       // head of these cols
        float gmax = fdec(g_gmaxu[myh]);
        for (int nId = gw; nId < n; nId += GW) {
            const int* __restrict__ pl = g_perm + (size_t)nId * SLOTS;
            int cnt = g_deg[nId];
            float4 adn4 = __ldg(reinterpret_cast<const float4*>(g_ad) + nId);
            float adn = (myh == 0) ? adn4.x : (myh == 1) ? adn4.y : (myh == 2) ? adn4.z : adn4.w;
            float mx = lrelu(gmax + adn);

            float acc[8];
#pragma unroll
            for (int j = 0; j < 8; j++) acc[j] = 0.f;
            float den = 0.f;
            int T = cnt + 1;           // item cnt = self loop
            int e = h;
            for (; e + 2 < T; e += 4) {
                int i0 = e, i1 = e + 2;
                int s0 = (i0 < cnt) ? __ldg(pl + i0) : nId;
                int s1 = (i1 < cnt) ? __ldg(pl + i1) : nId;
                uint4 r0 = __ldg(hb4 + (size_t)s0 * 16 + li);
                uint4 r1 = __ldg(hb4 + (size_t)s1 * 16 + li);
                float w0 = __expf(lrelu(__ldg(&g_as[s0 * 4 + myh]) + adn) - mx);
                float w1 = __expf(lrelu(__ldg(&g_as[s1 * 4 + myh]) + adn) - mx);
                den += w0 + w1;
                float2 p;
                p = bf2f(r0.x); acc[0] += w0 * p.x; acc[1] += w0 * p.y;
                p = bf2f(r0.y); acc[2] += w0 * p.x; acc[3] += w0 * p.y;
                p = bf2f(r0.z); acc[4] += w0 * p.x; acc[5] += w0 * p.y;
                p = bf2f(r0.w); acc[6] += w0 * p.x; acc[7] += w0 * p.y;
                p = bf2f(r1.x); acc[0] += w1 * p.x; acc[1] += w1 * p.y;
                p = bf2f(r1.y); acc[2] += w1 * p.x; acc[3] += w1 * p.y;
                p = bf2f(r1.z); acc[4] += w1 * p.x; acc[5] += w1 * p.y;
                p = bf2f(r1.w); acc[6] += w1 * p.x; acc[7] += w1 * p.y;
            }
            for (; e < T; e += 2) {
                int sn = (e < cnt) ? __ldg(pl + e) : nId;
                uint4 r = __ldg(hb4 + (size_t)sn * 16 + li);
                float w = __expf(lrelu(__ldg(&g_as[sn * 4 + myh]) + adn) - mx);
                den += w;
                float2 p;
                p = bf2f(r.x); acc[0] += w * p.x; acc[1] += w * p.y;
                p = bf2f(r.y); acc[2] += w * p.x; acc[3] += w * p.y;
                p = bf2f(r.z); acc[4] += w * p.x; acc[5] += w * p.y;
                p = bf2f(r.w); acc[6] += w * p.x; acc[7] += w * p.y;
            }
            __syncwarp();
            // combine halves (same cols, different edges)
            den += __shfl_xor_sync(0xffffffffu, den, 16);
#pragma unroll
            for (int j = 0; j < 8; j++) acc[j] += __shfl_xor_sync(0xffffffffu, acc[j], 16);
            float inv = 1.f / den;
#pragma unroll
            for (int j = 0; j < 8; j++) acc[j] *= inv;
            // mean over heads: sum lanes li, li^4, li^8 (li^12)
#pragma unroll
            for (int j = 0; j < 8; j++) {
                acc[j] += __shfl_xor_sync(0xffffffffu, acc[j], 4);
                acc[j] += __shfl_xor_sync(0xffffffffu, acc[j], 8);
            }
            if (lane < 4) {    // cols 8*lane + j
                float4 bg0 = __ldg(reinterpret_cast<const float4*>(bg) + 2 * lane);
                float4 bg1 = __ldg(reinterpret_cast<const float4*>(bg) + 2 * lane + 1);
                int b = __ldg(batch + nId);
                float* p = &g_pool[b * 32 + lane * 8];
                atomicAdd(p + 0, fmaxf(acc[0] * 0.25f + bg0.x, 0.f));
                atomicAdd(p + 1, fmaxf(acc[1] * 0.25f + bg0.y, 0.f));
                atomicAdd(p + 2, fmaxf(acc[2] * 0.25f + bg0.z, 0.f));
                atomicAdd(p + 3, fmaxf(acc[3] * 0.25f + bg0.w, 0.f));
                atomicAdd(p + 4, fmaxf(acc[4] * 0.25f + bg1.x, 0.f));
                atomicAdd(p + 5, fmaxf(acc[5] * 0.25f + bg1.y, 0.f));
                atomicAdd(p + 6, fmaxf(acc[6] * 0.25f + bg1.z, 0.f));
                atomicAdd(p + 7, fmaxf(acc[7] * 0.25f + bg1.w, 0.f));
                if (lane == 0) atomicAdd(&g_cnt[b], 1.f);
            }
        }
    }
    gridbar();

    // S12: classifier head (block 0 only)
    if (blockIdx.x == 0) {
        float* pooled = smw;
        float* hid = smw + GMAX * 32;
        for (int t = tid; t < G * 32; t += NTHR) pooled[t] = g_pool[t] / fmaxf(g_cnt[t >> 5], 1.f);
        __syncthreads();
        for (int t = tid; t < G * 16; t += NTHR) {
            int g = t >> 4, j = t & 15;
            float s = __ldg(bc1 + j);
            for (int k = 0; k < 32; k++) s += pooled[g * 32 + k] * __ldg(Wc1 + k * 16 + j);
            hid[t] = fmaxf(s, 0.f);
        }
        __syncthreads();
        for (int t = tid; t < G * 5; t += NTHR) {
            int g = t / 5, c = t % 5;
            float s = __ldg(bc2 + c);
            for (int k = 0; k < 16; k++) s += hid[g * 16 + k] * __ldg(Wc2 + k * 5 + c);
            out[t] = s;
        }
    }
}

// ---------------- host ----------------
extern "C" void kernel_launch(void* const* d_in, const int* in_sizes, int n_in,
                              void* d_out, int out_size) {
    const float* x = (const float*)d_in[0];
    const int* ei = (const int*)d_in[1];
    const int* batch = (const int*)d_in[2];
    int n = in_sizes[0] / 64;
    int E = in_sizes[1] / 2;
    int G = out_size / 5;

    const float *W1, *b1, *W2, *b2, *W3, *b3;
    const float *g1, *be1, *m1, *v1, *g2, *be2, *m2, *v2, *g3, *be3, *m3, *v3;
    const float *Wg, *ags, *agd, *bg, *Wc1, *bc1, *Wc2, *bc2;

    if (in_sizes[5] == 128 * 64) {
        W1 = (const float*)d_in[3];  b1 = (const float*)d_in[4];
        W2 = (const float*)d_in[5];  b2 = (const float*)d_in[6];
        W3 = (const float*)d_in[7];  b3 = (const float*)d_in[8];
        g1 = (const float*)d_in[9];  be1 = (const float*)d_in[10];
        m1 = (const float*)d_in[11]; v1 = (const float*)d_in[12];
        g2 = (const float*)d_in[13]; be2 = (const float*)d_in[14];
        m2 = (const float*)d_in[15]; v2 = (const float*)d_in[16];
        g3 = (const float*)d_in[17]; be3 = (const float*)d_in[18];
        m3 = (const float*)d_in[19]; v3 = (const float*)d_in[20];
        Wg = (const float*)d_in[21]; ags = (const float*)d_in[22];
        agd = (const float*)d_in[23]; bg = (const float*)d_in[24];
        Wc1 = (const float*)d_in[25]; bc1 = (const float*)d_in[26];
        Wc2 = (const float*)d_in[27]; bc2 = (const float*)d_in[28];
    } else {
        W1 = (const float*)d_in[3];  b1 = (const float*)d_in[4];
        g1 = (const float*)d_in[5];  be1 = (const float*)d_in[6];
        m1 = (const float*)d_in[7];  v1 = (const float*)d_in[8];
        W2 = (const float*)d_in[9];  b2 = (const float*)d_in[10];
        g2 = (const float*)d_in[11]; be2 = (const float*)d_in[12];
        m2 = (const float*)d_in[13]; v2 = (const float*)d_in[14];
        W3 = (const float*)d_in[15]; b3 = (const float*)d_in[16];
        g3 = (const float*)d_in[17]; be3 = (const float*)d_in[18];
        m3 = (const float*)d_in[19]; v3 = (const float*)d_in[20];
        Wg = (const float*)d_in[21]; ags = (const float*)d_in[22];
        agd = (const float*)d_in[23]; bg = (const float*)d_in[24];
        Wc1 = (const float*)d_in[25]; bc1 = (const float*)d_in[26];
        Wc2 = (const float*)d_in[27]; bc2 = (const float*)d_in[28];
    }

    const int* src = ei;
    const int* dst = ei + E;

    k_mega<<<NBLK, NTHR>>>(x, src, dst, batch, n, E, G,
                           W1, b1, g1, be1, m1, v1,
                           W2, b2, g2, be2, m2, v2,
                           W3, b3, g3, be3, m3, v3,
                           Wg, ags, agd, bg,
                           Wc1, bc1, Wc2, bc2,
                           (float*)d_out);
}

// round 14
// speedup vs baseline: 1.4106x; 1.4106x over previous
#include <cuda_runtime.h>
#include <cuda_bf16.h>
#include <math_constants.h>

#define NMAX 100000
#define GMAX 64
#define SLOTS 64
#define EPS 1e-5f
#define NEG_SLOPE 0.2f
#define NBLK 592          // 148 SMs x 4 blocks, all co-resident
#define NTHR 256

// ---------------- scratch (device globals) ----------------
__device__ __align__(16) unsigned g_B128[NMAX * 64];  // bf16x2, 128 cols/node
__device__ __align__(16) unsigned g_B64a[NMAX * 32];  // bf16x2, up to 64 cols/node
__device__ __align__(16) unsigned g_B64b[NMAX * 32];
__device__ float g_dinv[NMAX];
__device__ int   g_deg[NMAX];
__device__ int   g_cursor[NMAX];
__device__ int   g_perm[NMAX * SLOTS];
__device__ __align__(16) float g_as[NMAX * 4];
__device__ __align__(16) float g_ad[NMAX * 4];
__device__ float g_pool[GMAX * 32];
__device__ float g_cnt[GMAX];
__device__ unsigned g_gmaxu[4];
__device__ unsigned g_gen  = 0;
__device__ unsigned g_bcnt = 0;

// ---------------- grid-wide barrier (volatile-load polling) ----------------
__device__ __forceinline__ void gridbar() {
    __syncthreads();
    if (threadIdx.x == 0) {
        unsigned my = *(volatile unsigned*)&g_gen;
        __threadfence();
        if (atomicAdd(&g_bcnt, 1u) == NBLK - 1u) {
            atomicExch(&g_bcnt, 0u);
            __threadfence();
            atomicAdd(&g_gen, 1u);
        } else {
            while (*(volatile unsigned*)&g_gen == my) __nanosleep(64);
        }
        __threadfence();
    }
    __syncthreads();
}

__device__ __forceinline__ float lrelu(float x) { return x > 0.f ? x : NEG_SLOPE * x; }
__device__ __forceinline__ float2 bf2f(unsigned u) {
    return __bfloat1622float2(*reinterpret_cast<const __nv_bfloat162*>(&u));
}
__device__ __forceinline__ unsigned f2bf(float a, float b) {
    __nv_bfloat162 p = __floats2bfloat162_rn(a, b);
    return *reinterpret_cast<unsigned*>(&p);
}
__device__ __forceinline__ unsigned f2tf(float f) {
    unsigned u;
    asm("cvt.rna.tf32.f32 %0, %1;" : "=r"(u) : "f"(f));
    return u;
}
__device__ __forceinline__ unsigned fenc(float f) {
    int b = __float_as_int(f);
    return (b >= 0) ? ((unsigned)b | 0x80000000u) : (unsigned)(~b);
}
__device__ __forceinline__ float fdec(unsigned k) {
    return (k & 0x80000000u) ? __int_as_float((int)(k & 0x7FFFFFFFu))
                             : __int_as_float((int)~k);
}

__shared__ __align__(16) float smw[10240];   // 40KB stage scratch

// ---------------- tensor-core MMA m16n8k8 tf32 -> fp32 ----------------
__device__ __forceinline__ void mma1688(float c[4], unsigned a0, unsigned a1,
                                        unsigned a2, unsigned a3, unsigned b0, unsigned b1) {
    asm volatile(
        "mma.sync.aligned.m16n8k8.row.col.f32.tf32.tf32.f32 "
        "{%0,%1,%2,%3}, {%4,%5,%6,%7}, {%8,%9}, {%0,%1,%2,%3};"
        : "+f"(c[0]), "+f"(c[1]), "+f"(c[2]), "+f"(c[3])
        : "r"(a0), "r"(a1), "r"(a2), "r"(a3), "r"(b0), "r"(b1));
}

// ---------------- GEMM via tf32 MMA: A bf16 -> C bf16, opt bias+BN+relu, opt row-scale ----------------
template <int KIN, int KOUT, bool EPI, bool RSC>
__device__ void stage_mma(const unsigned* __restrict__ Ab, unsigned* __restrict__ Cb,
                          const float* __restrict__ W, int n, int lane, int gw, int GW,
                          const float* __restrict__ bias, const float* __restrict__ gam,
                          const float* __restrict__ bet, const float* __restrict__ mu,
                          const float* __restrict__ var) {
    constexpr int KS = KIN / 8;
    constexpr int NT = KOUT / 8;
    constexpr int JT = (NT >= 8) ? 8 : NT;
    constexpr int CHUNKS = NT / JT;
    constexpr int KIN2 = KIN / 2;
    constexpr int KOUT2 = KOUT / 2;

    uint2* bsm = reinterpret_cast<uint2*>(smw);
    for (int i = threadIdx.x; i < NT * KS * 32; i += NTHR) {
        int j = i / (KS * 32);
        int rem = i - j * (KS * 32);
        int s = rem >> 5;
        int l = rem & 31;
        int c_ = l & 3, nn = 8 * j + (l >> 2);
        int k0 = 8 * s + c_;
        unsigned v0 = f2tf(__ldg(W + k0 * KOUT + nn));
        unsigned v1 = f2tf(__ldg(W + (k0 + 4) * KOUT + nn));
        bsm[i] = make_uint2(v0, v1);
    }
    float* epiA = smw + 8192;
    float* epiB = smw + 8192 + KOUT;
    if constexpr (EPI) {
        for (int cix = threadIdx.x; cix < KOUT; cix += NTHR) {
            float Av = __ldg(gam + cix) * rsqrtf(__ldg(var + cix) + EPS);
            epiA[cix] = Av;
            epiB[cix] = __ldg(bet + cix) + (__ldg(bias + cix) - __ldg(mu + cix)) * Av;
        }
    }
    __syncthreads();

    int nrt = (n + 15) >> 4;
    int c = lane & 3, q = lane >> 2;
    int hw = c >> 1;
    bool hi = (c & 1);
    for (int T = gw; T < nrt * CHUNKS; T += GW) {
        int rt = (CHUNKS == 1) ? T : (T / CHUNKS);
        int ch = (CHUNKS == 1) ? 0 : (T - rt * CHUNKS);
        int r0 = rt * 16 + q;
        int r1 = r0 + 8;
        int rA = r0 < n ? r0 : n - 1;
        int rB = r1 < n ? r1 : n - 1;
        const unsigned* arow0 = Ab + (size_t)rA * KIN2;
        const unsigned* arow1 = Ab + (size_t)rB * KIN2;
        float acc[JT][4];
#pragma unroll
        for (int jj = 0; jj < JT; jj++) {
            acc[jj][0] = 0.f; acc[jj][1] = 0.f; acc[jj][2] = 0.f; acc[jj][3] = 0.f;
        }
#pragma unroll
        for (int s = 0; s < KS; s++) {
            unsigned wa0 = __ldg(arow0 + 4 * s + hw);
            unsigned wa1 = __ldg(arow0 + 4 * s + 2 + hw);
            unsigned wb0 = __ldg(arow1 + 4 * s + hw);
            unsigned wb1 = __ldg(arow1 + 4 * s + 2 + hw);
            unsigned a0 = hi ? (wa0 & 0xFFFF0000u) : (wa0 << 16);
            unsigned a2 = hi ? (wa1 & 0xFFFF0000u) : (wa1 << 16);
            unsigned a1 = hi ? (wb0 & 0xFFFF0000u) : (wb0 << 16);
            unsigned a3 = hi ? (wb1 & 0xFFFF0000u) : (wb1 << 16);
#pragma unroll
            for (int jj = 0; jj < JT; jj++) {
                uint2 bb = bsm[((ch * JT + jj) * KS + s) * 32 + lane];
                mma1688(acc[jj], a0, a1, a2, a3, bb.x, bb.y);
            }
        }
        float dr0 = 1.f, dr1 = 1.f;
        if constexpr (RSC) {
            dr0 = __ldg(g_dinv + rA);
            dr1 = __ldg(g_dinv + rB);
        }
#pragma unroll
        for (int jj = 0; jj < JT; jj++) {
            int col0 = 8 * (ch * JT + jj) + 2 * c;
            float x0 = acc[jj][0], x1 = acc[jj][1], x2 = acc[jj][2], x3 = acc[jj][3];
            if constexpr (EPI) {
                float A0 = epiA[col0], B0 = epiB[col0];
                float A1 = epiA[col0 + 1], B1 = epiB[col0 + 1];
                x0 = fmaxf(x0 * A0 + B0, 0.f); x1 = fmaxf(x1 * A1 + B1, 0.f);
                x2 = fmaxf(x2 * A0 + B0, 0.f); x3 = fmaxf(x3 * A1 + B1, 0.f);
            }
            if constexpr (RSC) {
                x0 *= dr0; x1 *= dr0; x2 *= dr1; x3 *= dr1;
            }
            int ci = col0 >> 1;
            if (r0 < n) Cb[(size_t)r0 * KOUT2 + ci] = f2bf(x0, x1);
            if (r1 < n) Cb[(size_t)r1 * KOUT2 + ci] = f2bf(x2, x3);
        }
    }
}

// ---------------- GCN agg (D=64), PRESCALED features: pure adds, dual-edge half-warps ----------------
template <bool EPIL>
__device__ void stage_agg64(const unsigned* __restrict__ featb, unsigned* __restrict__ outb, int n,
                            int lane, int gw, int GW,
                            const float* __restrict__ bias, const float* __restrict__ gam,
                            const float* __restrict__ bet, const float* __restrict__ mu,
                            const float* __restrict__ var) {
    const uint2* fb = reinterpret_cast<const uint2*>(featb);
    uint2* ob = reinterpret_cast<uint2*>(outb);
    int h = lane >> 4;
    int li = lane & 15;
    float A0 = 1.f, A1 = 1.f, A2 = 1.f, A3 = 1.f, B0 = 0.f, B1 = 0.f, B2 = 0.f, B3 = 0.f;
    if constexpr (EPIL) {
        int d = 4 * li;
        A0 = __ldg(gam + d + 0) * rsqrtf(__ldg(var + d + 0) + EPS);
        B0 = __ldg(bet + d + 0) + (__ldg(bias + d + 0) - __ldg(mu + d + 0)) * A0;
        A1 = __ldg(gam + d + 1) * rsqrtf(__ldg(var + d + 1) + EPS);
        B1 = __ldg(bet + d + 1) + (__ldg(bias + d + 1) - __ldg(mu + d + 1)) * A1;
        A2 = __ldg(gam + d + 2) * rsqrtf(__ldg(var + d + 2) + EPS);
        B2 = __ldg(bet + d + 2) + (__ldg(bias + d + 2) - __ldg(mu + d + 2)) * A2;
        A3 = __ldg(gam + d + 3) * rsqrtf(__ldg(var + d + 3) + EPS);
        B3 = __ldg(bet + d + 3) + (__ldg(bias + d + 3) - __ldg(mu + d + 3)) * A3;
    }
    for (int w = gw; w < n; w += GW) {
        float di = g_dinv[w];
        int cnt = g_deg[w];
        const int* __restrict__ pl = g_perm + (size_t)w * SLOTS;
        float a0, a1, a2, a3;
        if (h == 0) {
            uint2 v = __ldg(fb + (size_t)w * 16 + li);
            float2 p0 = bf2f(v.x), p1 = bf2f(v.y);
            a0 = p0.x; a1 = p0.y; a2 = p1.x; a3 = p1.y;
        } else {
            a0 = 0.f; a1 = 0.f; a2 = 0.f; a3 = 0.f;
        }
        int e = h;
#pragma unroll 2
        for (; e + 6 < cnt; e += 8) {
            int s0 = __ldg(pl + e), s1 = __ldg(pl + e + 2);
            int s2 = __ldg(pl + e + 4), s3 = __ldg(pl + e + 6);
            uint2 v0 = __ldg(fb + (size_t)s0 * 16 + li);
            uint2 v1 = __ldg(fb + (size_t)s1 * 16 + li);
            uint2 v2 = __ldg(fb + (size_t)s2 * 16 + li);
            uint2 v3 = __ldg(fb + (size_t)s3 * 16 + li);
            float2 p;
            p = bf2f(v0.x); a0 += p.x; a1 += p.y;  p = bf2f(v0.y); a2 += p.x; a3 += p.y;
            p = bf2f(v1.x); a0 += p.x; a1 += p.y;  p = bf2f(v1.y); a2 += p.x; a3 += p.y;
            p = bf2f(v2.x); a0 += p.x; a1 += p.y;  p = bf2f(v2.y); a2 += p.x; a3 += p.y;
            p = bf2f(v3.x); a0 += p.x; a1 += p.y;  p = bf2f(v3.y); a2 += p.x; a3 += p.y;
        }
        for (; e < cnt; e += 2) {
            int sn = __ldg(pl + e);
            uint2 v = __ldg(fb + (size_t)sn * 16 + li);
            float2 p0 = bf2f(v.x), p1 = bf2f(v.y);
            a0 += p0.x; a1 += p0.y; a2 += p1.x; a3 += p1.y;
        }
        __syncwarp();
        a0 += __shfl_down_sync(0xffffffffu, a0, 16);
        a1 += __shfl_down_sync(0xffffffffu, a1, 16);
        a2 += __shfl_down_sync(0xffffffffu, a2, 16);
        a3 += __shfl_down_sync(0xffffffffu, a3, 16);
        if (lane < 16) {
            float o0, o1, o2, o3;
            if constexpr (EPIL) {
                o0 = fmaxf(a0 * (di * A0) + B0, 0.f);
                o1 = fmaxf(a1 * (di * A1) + B1, 0.f);
                o2 = fmaxf(a2 * (di * A2) + B2, 0.f);
                o3 = fmaxf(a3 * (di * A3) + B3, 0.f);
            } else {
                o0 = a0 * di; o1 = a1 * di; o2 = a2 * di; o3 = a3 * di;
            }
            ob[(size_t)w * 16 + li] = make_uint2(f2bf(o0, o1), f2bf(o2, o3));
        }
    }
}

// ---------------- GCN agg (D=32), PRESCALED, two nodes per warp, bf16 out + BN epilogue ----------------
__device__ void stage_agg32_dual(const unsigned* __restrict__ featb, unsigned* __restrict__ outb, int n,
                                 int lane, int gw, int GW,
                                 const float* __restrict__ bias, const float* __restrict__ gam,
                                 const float* __restrict__ bet, const float* __restrict__ mu,
                                 const float* __restrict__ var) {
    int sub = lane >> 4;
    int li = lane & 15;
    int d0 = 2 * li, d1 = 2 * li + 1;
    float A0 = __ldg(gam + d0) * rsqrtf(__ldg(var + d0) + EPS);
    float B0 = __ldg(bet + d0) + (__ldg(bias + d0) - __ldg(mu + d0)) * A0;
    float A1 = __ldg(gam + d1) * rsqrtf(__ldg(var + d1) + EPS);
    float B1 = __ldg(bet + d1) + (__ldg(bias + d1) - __ldg(mu + d1)) * A1;

    for (int base = gw * 2; base < n; base += GW * 2) {
        int w = base + sub;
        bool valid = w < n;
        int wc = valid ? w : n - 1;
        float di = g_dinv[wc];
        int cnt = g_deg[wc];
        int cnto = __shfl_xor_sync(0xffffffffu, cnt, 16);
        int cmax = cnt > cnto ? cnt : cnto;
        const int* __restrict__ pl = g_perm + (size_t)wc * SLOTS;
        float ax, ay;
        {
            float2 v = bf2f(__ldg(featb + (size_t)wc * 16 + li));
            ax = v.x; ay = v.y;
        }
        int e = 0;
        for (; e + 4 <= cmax; e += 4) {
            int s[4]; float g[4]; unsigned r[4];
#pragma unroll
            for (int u = 0; u < 4; u++) {
                bool a = (e + u) < cnt;
                s[u] = a ? __ldg(pl + e + u) : wc;
                g[u] = a ? 1.f : 0.f;
            }
#pragma unroll
            for (int u = 0; u < 4; u++) r[u] = __ldg(featb + (size_t)s[u] * 16 + li);
#pragma unroll
            for (int u = 0; u < 4; u++) {
                float2 v = bf2f(r[u]);
                ax += g[u] * v.x; ay += g[u] * v.y;
            }
        }
        for (; e < cmax; e++) {
            bool a = e < cnt;
            int sn = a ? __ldg(pl + e) : wc;
            float g = a ? 1.f : 0.f;
            float2 v = bf2f(__ldg(featb + (size_t)sn * 16 + li));
            ax += g * v.x; ay += g * v.y;
        }
        ax = fmaxf(ax * (di * A0) + B0, 0.f);
        ay = fmaxf(ay * (di * A1) + B1, 0.f);
        if (valid) outb[(size_t)w * 16 + li] = f2bf(ax, ay);
    }
}

// ---------------- the megakernel ----------------
__global__ void __launch_bounds__(NTHR, 4)
k_mega(const float* __restrict__ x, const int* __restrict__ src, const int* __restrict__ dst,
       const int* __restrict__ batch, int n, int E, int G,
       const float* W1, const float* b1, const float* g1, const float* be1, const float* m1, const float* v1,
       const float* W2, const float* b2, const float* g2, const float* be2, const float* m2, const float* v2,
       const float* W3, const float* b3, const float* g3, const float* be3, const float* m3, const float* v3,
       const float* Wg, const float* ags, const float* agd, const float* bg,
       const float* Wc1, const float* bc1, const float* Wc2, const float* bc2,
       float* __restrict__ out) {
    int tid = threadIdx.x;
    int lane = tid & 31;
    int gt = blockIdx.x * NTHR + tid;
    int gw = gt >> 5;
    const int GT = NBLK * NTHR;
    const int GW = GT / 32;

    // S0: zero cursors/pool/cnt/gmax
    for (int i = gt; i < n; i += GT) g_cursor[i] = 0;
    if (gt < GMAX * 32) g_pool[gt] = 0.f;
    if (gt < GMAX) g_cnt[gt] = 0.f;
    if (gt < 4) g_gmaxu[gt] = 0u;
    gridbar();

    // S1: bucket scatter by dst
    for (int e = gt; e < E; e += GT) {
        int d = dst[e];
        int slot = atomicAdd(&g_cursor[d], 1);
        if (slot < SLOTS) g_perm[(size_t)d * SLOTS + slot] = src[e];
    }
    gridbar();

    // S2: finalize degree/dinv + convert x -> prescaled bf16
    for (int i = gt; i < n; i += GT) {
        int c = g_cursor[i];
        if (c > SLOTS) c = SLOTS;
        g_deg[i] = c;
        g_dinv[i] = rsqrtf((float)(c + 1));
    }
    for (int i = gt; i < n * 32; i += GT) {
        int node = i >> 5;
        int c = g_cursor[node];
        if (c > SLOTS) c = SLOTS;
        float di = rsqrtf((float)(c + 1));
        g_B64a[i] = f2bf(di * __ldg(x + 2 * i), di * __ldg(x + 2 * i + 1));
    }
    gridbar();

    // S3: aggregate prescaled input (linearity), out = bf16(di*acc)
    stage_agg64<false>(g_B64a, g_B64b, n, lane, gw, GW, nullptr, nullptr, nullptr, nullptr, nullptr);
    gridbar();

    // S4: tf32 GEMM 64->128 + bias/BN/relu
    stage_mma<64, 128, true, false>(g_B64b, g_B128, W1, n, lane, gw, GW, b1, g1, be1, m1, v1);
    gridbar();

    // S5: tf32 GEMM 128->64, out prescaled by dinv
    stage_mma<128, 64, false, true>(g_B128, g_B64a, W2, n, lane, gw, GW, nullptr, nullptr, nullptr, nullptr, nullptr);
    gridbar();

    // S6: aggregate + bias/BN/relu (di folded into epilogue)
    stage_agg64<true>(g_B64a, g_B64b, n, lane, gw, GW, b2, g2, be2, m2, v2);
    gridbar();

    // S7: tf32 GEMM 64->32, out prescaled by dinv
    stage_mma<64, 32, false, true>(g_B64b, g_B64a, W3, n, lane, gw, GW, nullptr, nullptr, nullptr, nullptr, nullptr);
    gridbar();

    // S8: aggregate + bias/BN/relu (32-dim), two nodes/warp
    stage_agg32_dual(g_B64a, g_B64b, n, lane, gw, GW, b3, g3, be3, m3, v3);
    gridbar();

    // S9: tf32 GEMM 32->128 (GAT projection), unscaled bf16 out
    stage_mma<32, 128, false, false>(g_B64b, g_B128, Wg, n, lane, gw, GW, nullptr, nullptr, nullptr, nullptr, nullptr);
    gridbar();

    // S10: attention coefficients from bf16 hh + per-head global max
    {
        unsigned* gm = reinterpret_cast<unsigned*>(smw);
        if (tid < 4) gm[tid] = 0u;
        __syncthreads();
        const float4* ags4 = reinterpret_cast<const float4*>(ags);
        const float4* agd4 = reinterpret_cast<const float4*>(agd);
        float4 sg = __ldg(ags4 + lane);
        float4 dg = __ldg(agd4 + lane);
        const uint2* hb = reinterpret_cast<const uint2*>(g_B128);
        float smax = -CUDART_INF_F;
        for (int node = gw; node < n; node += GW) {
            uint2 w = __ldg(hb + (size_t)node * 32 + lane);
            float2 p0 = bf2f(w.x), p1 = bf2f(w.y);
            float s = p0.x * sg.x + p0.y * sg.y + p1.x * sg.z + p1.y * sg.w;
            float d = p0.x * dg.x + p0.y * dg.y + p1.x * dg.z + p1.y * dg.w;
#pragma unroll
            for (int off = 4; off; off >>= 1) {
                s += __shfl_xor_sync(0xffffffffu, s, off);
                d += __shfl_xor_sync(0xffffffffu, d, off);
            }
            if ((lane & 7) == 0) {
                int h = lane >> 3;
                g_as[node * 4 + h] = s;
                g_ad[node * 4 + h] = d;
            }
            smax = fmaxf(smax, s);
        }
        if ((lane & 7) == 0) atomicMax(&gm[lane >> 3], fenc(smax));
        __syncthreads();
        if (tid < 4) atomicMax(&g_gmaxu[tid], gm[tid]);
    }
    gridbar();

    // S11: GAT aggregation (bf16 gather, global-max softmax) + bias/relu + fused pool
    {
        const uint2* hb = reinterpret_cast<const uint2*>(g_B128);
        int myh = lane >> 3;
        float gmax = fdec(g_gmaxu[myh]);
        for (int nId = gw; nId < n; nId += GW) {
            const int* __restrict__ pl = g_perm + (size_t)nId * SLOTS;
            int cnt = g_deg[nId];
            float4 adn4 = __ldg(reinterpret_cast<const float4*>(g_ad) + nId);
            float adn = (myh == 0) ? adn4.x : (myh == 1) ? adn4.y : (myh == 2) ? adn4.z : adn4.w;
            float mx = lrelu(gmax + adn);

            float4 acc = make_float4(0.f, 0.f, 0.f, 0.f);
            float den = 0.f;
            int e = 0;
#pragma unroll 2
            for (; e + 4 <= cnt; e += 4) {
                int s0 = __ldg(pl + e + 0), s1 = __ldg(pl + e + 1);
                int s2 = __ldg(pl + e + 2), s3 = __ldg(pl + e + 3);
                uint2 r0 = __ldg(hb + (size_t)s0 * 32 + lane);
                uint2 r1 = __ldg(hb + (size_t)s1 * 32 + lane);
                uint2 r2 = __ldg(hb + (size_t)s2 * 32 + lane);
                uint2 r3 = __ldg(hb + (size_t)s3 * 32 + lane);
                float w0 = __expf(lrelu(__ldg(&g_as[s0 * 4 + myh]) + adn) - mx);
                float w1 = __expf(lrelu(__ldg(&g_as[s1 * 4 + myh]) + adn) - mx);
                float w2 = __expf(lrelu(__ldg(&g_as[s2 * 4 + myh]) + adn) - mx);
                float w3 = __expf(lrelu(__ldg(&g_as[s3 * 4 + myh]) + adn) - mx);
                den += (w0 + w1) + (w2 + w3);
                float2 a0 = bf2f(r0.x), b0 = bf2f(r0.y);
                float2 a1 = bf2f(r1.x), b1 = bf2f(r1.y);
                float2 a2 = bf2f(r2.x), b2 = bf2f(r2.y);
                float2 a3 = bf2f(r3.x), b3 = bf2f(r3.y);
                acc.x += w0 * a0.x + w1 * a1.x + w2 * a2.x + w3 * a3.x;
                acc.y += w0 * a0.y + w1 * a1.y + w2 * a2.y + w3 * a3.y;
                acc.z += w0 * b0.x + w1 * b1.x + w2 * b2.x + w3 * b3.x;
                acc.w += w0 * b0.y + w1 * b1.y + w2 * b2.y + w3 * b3.y;
            }
            for (; e <= cnt; e++) {
                int sn = (e < cnt) ? __ldg(pl + e) : nId;
                float w = __expf(lrelu(__ldg(&g_as[sn * 4 + myh]) + adn) - mx);
                den += w;
                uint2 r = __ldg(hb + (size_t)sn * 32 + lane);
                float2 a = bf2f(r.x), b = bf2f(r.y);
                acc.x += w * a.x; acc.y += w * a.y; acc.z += w * b.x; acc.w += w * b.y;
            }
            float inv = 1.f / den;
            acc.x *= inv; acc.y *= inv; acc.z *= inv; acc.w *= inv;
#pragma unroll
            for (int off = 8; off <= 16; off <<= 1) {
                acc.x += __shfl_xor_sync(0xffffffffu, acc.x, off);
                acc.y += __shfl_xor_sync(0xffffffffu, acc.y, off);
                acc.z += __shfl_xor_sync(0xffffffffu, acc.z, off);
                acc.w += __shfl_xor_sync(0xffffffffu, acc.w, off);
            }
            if (lane < 8) {
                float4 bgv = __ldg(reinterpret_cast<const float4*>(bg) + lane);
                int b = __ldg(batch + nId);
                float* p = &g_pool[b * 32 + lane * 4];
                atomicAdd(p + 0, fmaxf(acc.x * 0.25f + bgv.x, 0.f));
                atomicAdd(p + 1, fmaxf(acc.y * 0.25f + bgv.y, 0.f));
                atomicAdd(p + 2, fmaxf(acc.z * 0.25f + bgv.z, 0.f));
                atomicAdd(p + 3, fmaxf(acc.w * 0.25f + bgv.w, 0.f));
                if (lane == 0) atomicAdd(&g_cnt[b], 1.f);
            }
        }
    }
    gridbar();

    // S12: classifier head (block 0 only)
    if (blockIdx.x == 0) {
        float* pooled = smw;
        float* hid = smw + GMAX * 32;
        for (int t = tid; t < G * 32; t += NTHR) pooled[t] = g_pool[t] / fmaxf(g_cnt[t >> 5], 1.f);
        __syncthreads();
        for (int t = tid; t < G * 16; t += NTHR) {
            int g = t >> 4, j = t & 15;
            float s = __ldg(bc1 + j);
            for (int k = 0; k < 32; k++) s += pooled[g * 32 + k] * __ldg(Wc1 + k * 16 + j);
            hid[t] = fmaxf(s, 0.f);
        }
        __syncthreads();
        for (int t = tid; t < G * 5; t += NTHR) {
            int g = t / 5, c = t % 5;
            float s = __ldg(bc2 + c);
            for (int k = 0; k < 16; k++) s += hid[g * 16 + k] * __ldg(Wc2 + k * 5 + c);
            out[t] = s;
        }
    }
}

// ---------------- host ----------------
extern "C" void kernel_launch(void* const* d_in, const int* in_sizes, int n_in,
                              void* d_out, int out_size) {
    const float* x = (const float*)d_in[0];
    const int* ei = (const int*)d_in[1];
    const int* batch = (const int*)d_in[2];
    int n = in_sizes[0] / 64;
    int E = in_sizes[1] / 2;
    int G = out_size / 5;

    const float *W1, *b1, *W2, *b2, *W3, *b3;
    const float *g1, *be1, *m1, *v1, *g2, *be2, *m2, *v2, *g3, *be3, *m3, *v3;
    const float *Wg, *ags, *agd, *bg, *Wc1, *bc1, *Wc2, *bc2;

    if (in_sizes[5] == 128 * 64) {
        W1 = (const float*)d_in[3];  b1 = (const float*)d_in[4];
        W2 = (const float*)d_in[5];  b2 = (const float*)d_in[6];
        W3 = (const float*)d_in[7];  b3 = (const float*)d_in[8];
        g1 = (const float*)d_in[9];  be1 = (const float*)d_in[10];
        m1 = (const float*)d_in[11]; v1 = (const float*)d_in[12];
        g2 = (const float*)d_in[13]; be2 = (const float*)d_in[14];
        m2 = (const float*)d_in[15]; v2 = (const float*)d_in[16];
        g3 = (const float*)d_in[17]; be3 = (const float*)d_in[18];
        m3 = (const float*)d_in[19]; v3 = (const float*)d_in[20];
        Wg = (const float*)d_in[21]; ags = (const float*)d_in[22];
        agd = (const float*)d_in[23]; bg = (const float*)d_in[24];
        Wc1 = (const float*)d_in[25]; bc1 = (const float*)d_in[26];
        Wc2 = (const float*)d_in[27]; bc2 = (const float*)d_in[28];
    } else {
        W1 = (const float*)d_in[3];  b1 = (const float*)d_in[4];
        g1 = (const float*)d_in[5];  be1 = (const float*)d_in[6];
        m1 = (const float*)d_in[7];  v1 = (const float*)d_in[8];
        W2 = (const float*)d_in[9];  b2 = (const float*)d_in[10];
        g2 = (const float*)d_in[11]; be2 = (const float*)d_in[12];
        m2 = (const float*)d_in[13]; v2 = (const float*)d_in[14];
        W3 = (const float*)d_in[15]; b3 = (const float*)d_in[16];
        g3 = (const float*)d_in[17]; be3 = (const float*)d_in[18];
        m3 = (const float*)d_in[19]; v3 = (const float*)d_in[20];
        Wg = (const float*)d_in[21]; ags = (const float*)d_in[22];
        agd = (const float*)d_in[23]; bg = (const float*)d_in[24];
        Wc1 = (const float*)d_in[25]; bc1 = (const float*)d_in[26];
        Wc2 = (const float*)d_in[27]; bc2 = (const float*)d_in[28];
    }

    const int* src = ei;
    const int* dst = ei + E;

    k_mega<<<NBLK, NTHR>>>(x, src, dst, batch, n, E, G,
                           W1, b1, g1, be1, m1, v1,
                           W2, b2, g2, be2, m2, v2,
                           W3, b3, g3, be3, m3, v3,
                           Wg, ags, agd, bg,
                           Wc1, bc1, Wc2, bc2,
                           (float*)d_out);
}

// round 15
// speedup vs baseline: 1.4234x; 1.0090x over previous
#include <cuda_runtime.h>
#include <cuda_bf16.h>
#include <math_constants.h>

#define NMAX 100000
#define GMAX 64
#define SLOTS 64
#define EPS 1e-5f
#define NEG_SLOPE 0.2f
#define NBLK 592          // 148 SMs x 4 blocks, all co-resident
#define NTHR 256

// ---------------- scratch (device globals) ----------------
__device__ __align__(16) unsigned g_B128[NMAX * 64];  // bf16x2, 128 cols/node (P matrix)
__device__ __align__(16) unsigned g_B64a[NMAX * 32];  // bf16x2, up to 64 cols/node
__device__ __align__(16) unsigned g_B64b[NMAX * 32];
__device__ float g_dinv[NMAX];
__device__ int   g_deg[NMAX];
__device__ int   g_cursor[NMAX];
__device__ int   g_perm[NMAX * SLOTS];
__device__ __align__(16) float g_as[NMAX * 4];
__device__ __align__(16) float g_ad[NMAX * 4];
__device__ float g_pool[GMAX * 32];
__device__ float g_cnt[GMAX];
__device__ unsigned g_gmaxu[4];
__device__ unsigned g_gen  = 0;
__device__ unsigned g_bcnt = 0;

// ---------------- grid-wide barrier (volatile-load polling) ----------------
__device__ __forceinline__ void gridbar() {
    __syncthreads();
    if (threadIdx.x == 0) {
        unsigned my = *(volatile unsigned*)&g_gen;
        __threadfence();
        if (atomicAdd(&g_bcnt, 1u) == NBLK - 1u) {
            atomicExch(&g_bcnt, 0u);
            __threadfence();
            atomicAdd(&g_gen, 1u);
        } else {
            while (*(volatile unsigned*)&g_gen == my) __nanosleep(64);
        }
        __threadfence();
    }
    __syncthreads();
}

__device__ __forceinline__ float lrelu(float x) { return x > 0.f ? x : NEG_SLOPE * x; }
__device__ __forceinline__ float2 bf2f(unsigned u) {
    return __bfloat1622float2(*reinterpret_cast<const __nv_bfloat162*>(&u));
}
__device__ __forceinline__ unsigned f2bf(float a, float b) {
    __nv_bfloat162 p = __floats2bfloat162_rn(a, b);
    return *reinterpret_cast<unsigned*>(&p);
}
__device__ __forceinline__ unsigned f2tf(float f) {
    unsigned u;
    asm("cvt.rna.tf32.f32 %0, %1;" : "=r"(u) : "f"(f));
    return u;
}
__device__ __forceinline__ unsigned fenc(float f) {
    int b = __float_as_int(f);
    return (b >= 0) ? ((unsigned)b | 0x80000000u) : (unsigned)(~b);
}
__device__ __forceinline__ float fdec(unsigned k) {
    return (k & 0x80000000u) ? __int_as_float((int)(k & 0x7FFFFFFFu))
                             : __int_as_float((int)~k);
}

__shared__ __align__(16) float smw[10240];   // 40KB stage scratch

// ---------------- tensor-core MMA m16n8k8 tf32 -> fp32 ----------------
__device__ __forceinline__ void mma1688(float c[4], unsigned a0, unsigned a1,
                                        unsigned a2, unsigned a3, unsigned b0, unsigned b1) {
    asm volatile(
        "mma.sync.aligned.m16n8k8.row.col.f32.tf32.tf32.f32 "
        "{%0,%1,%2,%3}, {%4,%5,%6,%7}, {%8,%9}, {%0,%1,%2,%3};"
        : "+f"(c[0]), "+f"(c[1]), "+f"(c[2]), "+f"(c[3])
        : "r"(a0), "r"(a1), "r"(a2), "r"(a3), "r"(b0), "r"(b1));
}

// ---------------- GEMM via tf32 MMA: A bf16 -> C bf16 ----------------
// EPIM: 0 none, 1 BN(bias+BN+relu), 2 bias+relu. RSC: row-scale by dinv.
// GATW: W is Wg[32,128] remapped to head-stacked [128,32] * 0.25 (GAT output GEMM).
template <int KIN, int KOUT, int EPIM, bool RSC, bool GATW>
__device__ void stage_mma(const unsigned* __restrict__ Ab, unsigned* __restrict__ Cb,
                          const float* __restrict__ W, int n, int lane, int gw, int GW,
                          const float* __restrict__ bias, const float* __restrict__ gam,
                          const float* __restrict__ bet, const float* __restrict__ mu,
                          const float* __restrict__ var) {
    constexpr int KS = KIN / 8;
    constexpr int NT = KOUT / 8;
    constexpr int JT = (NT >= 8) ? 8 : NT;
    constexpr int CHUNKS = NT / JT;
    constexpr int KIN2 = KIN / 2;
    constexpr int KOUT2 = KOUT / 2;

    uint2* bsm = reinterpret_cast<uint2*>(smw);
    for (int i = threadIdx.x; i < NT * KS * 32; i += NTHR) {
        int j = i / (KS * 32);
        int rem = i - j * (KS * 32);
        int s = rem >> 5;
        int l = rem & 31;
        int c_ = l & 3, nn = 8 * j + (l >> 2);
        int k0 = 8 * s + c_;
        float w0, w1;
        if constexpr (GATW) {
            // Wbig[k][nn] = 0.25 * Wg[k & 31][(k >> 5)*32 + nn]
            w0 = 0.25f * __ldg(W + (k0 & 31) * 128 + ((k0 >> 5) * 32 + nn));
            w1 = 0.25f * __ldg(W + ((k0 + 4) & 31) * 128 + (((k0 + 4) >> 5) * 32 + nn));
        } else {
            w0 = __ldg(W + k0 * KOUT + nn);
            w1 = __ldg(W + (k0 + 4) * KOUT + nn);
        }
        bsm[i] = make_uint2(f2tf(w0), f2tf(w1));
    }
    float* epiA = smw + 8192;
    float* epiB = smw + 8192 + KOUT;
    if constexpr (EPIM == 1) {
        for (int cix = threadIdx.x; cix < KOUT; cix += NTHR) {
            float Av = __ldg(gam + cix) * rsqrtf(__ldg(var + cix) + EPS);
            epiA[cix] = Av;
            epiB[cix] = __ldg(bet + cix) + (__ldg(bias + cix) - __ldg(mu + cix)) * Av;
        }
    } else if constexpr (EPIM == 2) {
        for (int cix = threadIdx.x; cix < KOUT; cix += NTHR)
            epiB[cix] = __ldg(bias + cix);
    }
    __syncthreads();

    int nrt = (n + 15) >> 4;
    int c = lane & 3, q = lane >> 2;
    int hw = c >> 1;
    bool hi = (c & 1);
    for (int T = gw; T < nrt * CHUNKS; T += GW) {
        int rt = (CHUNKS == 1) ? T : (T / CHUNKS);
        int ch = (CHUNKS == 1) ? 0 : (T - rt * CHUNKS);
        int r0 = rt * 16 + q;
        int r1 = r0 + 8;
        int rA = r0 < n ? r0 : n - 1;
        int rB = r1 < n ? r1 : n - 1;
        const unsigned* arow0 = Ab + (size_t)rA * KIN2;
        const unsigned* arow1 = Ab + (size_t)rB * KIN2;
        float acc[JT][4];
#pragma unroll
        for (int jj = 0; jj < JT; jj++) {
            acc[jj][0] = 0.f; acc[jj][1] = 0.f; acc[jj][2] = 0.f; acc[jj][3] = 0.f;
        }
#pragma unroll
        for (int s = 0; s < KS; s++) {
            unsigned wa0 = __ldg(arow0 + 4 * s + hw);
            unsigned wa1 = __ldg(arow0 + 4 * s + 2 + hw);
            unsigned wb0 = __ldg(arow1 + 4 * s + hw);
            unsigned wb1 = __ldg(arow1 + 4 * s + 2 + hw);
            unsigned a0 = hi ? (wa0 & 0xFFFF0000u) : (wa0 << 16);
            unsigned a2 = hi ? (wa1 & 0xFFFF0000u) : (wa1 << 16);
            unsigned a1 = hi ? (wb0 & 0xFFFF0000u) : (wb0 << 16);
            unsigned a3 = hi ? (wb1 & 0xFFFF0000u) : (wb1 << 16);
#pragma unroll
            for (int jj = 0; jj < JT; jj++) {
                uint2 bb = bsm[((ch * JT + jj) * KS + s) * 32 + lane];
                mma1688(acc[jj], a0, a1, a2, a3, bb.x, bb.y);
            }
        }
        float dr0 = 1.f, dr1 = 1.f;
        if constexpr (RSC) {
            dr0 = __ldg(g_dinv + rA);
            dr1 = __ldg(g_dinv + rB);
        }
#pragma unroll
        for (int jj = 0; jj < JT; jj++) {
            int col0 = 8 * (ch * JT + jj) + 2 * c;
            float x0 = acc[jj][0], x1 = acc[jj][1], x2 = acc[jj][2], x3 = acc[jj][3];
            if constexpr (EPIM == 1) {
                float A0 = epiA[col0], B0 = epiB[col0];
                float A1 = epiA[col0 + 1], B1 = epiB[col0 + 1];
                x0 = fmaxf(x0 * A0 + B0, 0.f); x1 = fmaxf(x1 * A1 + B1, 0.f);
                x2 = fmaxf(x2 * A0 + B0, 0.f); x3 = fmaxf(x3 * A1 + B1, 0.f);
            } else if constexpr (EPIM == 2) {
                float B0 = epiB[col0], B1 = epiB[col0 + 1];
                x0 = fmaxf(x0 + B0, 0.f); x1 = fmaxf(x1 + B1, 0.f);
                x2 = fmaxf(x2 + B0, 0.f); x3 = fmaxf(x3 + B1, 0.f);
            }
            if constexpr (RSC) {
                x0 *= dr0; x1 *= dr0; x2 *= dr1; x3 *= dr1;
            }
            int ci = col0 >> 1;
            if (r0 < n) Cb[(size_t)r0 * KOUT2 + ci] = f2bf(x0, x1);
            if (r1 < n) Cb[(size_t)r1 * KOUT2 + ci] = f2bf(x2, x3);
        }
    }
}

// ---------------- GCN agg (D=64), PRESCALED features: pure adds, dual-edge half-warps ----------------
template <bool EPIL>
__device__ void stage_agg64(const unsigned* __restrict__ featb, unsigned* __restrict__ outb, int n,
                            int lane, int gw, int GW,
                            const float* __restrict__ bias, const float* __restrict__ gam,
                            const float* __restrict__ bet, const float* __restrict__ mu,
                            const float* __restrict__ var) {
    const uint2* fb = reinterpret_cast<const uint2*>(featb);
    uint2* ob = reinterpret_cast<uint2*>(outb);
    int h = lane >> 4;
    int li = lane & 15;
    float A0 = 1.f, A1 = 1.f, A2 = 1.f, A3 = 1.f, B0 = 0.f, B1 = 0.f, B2 = 0.f, B3 = 0.f;
    if constexpr (EPIL) {
        int d = 4 * li;
        A0 = __ldg(gam + d + 0) * rsqrtf(__ldg(var + d + 0) + EPS);
        B0 = __ldg(bet + d + 0) + (__ldg(bias + d + 0) - __ldg(mu + d + 0)) * A0;
        A1 = __ldg(gam + d + 1) * rsqrtf(__ldg(var + d + 1) + EPS);
        B1 = __ldg(bet + d + 1) + (__ldg(bias + d + 1) - __ldg(mu + d + 1)) * A1;
        A2 = __ldg(gam + d + 2) * rsqrtf(__ldg(var + d + 2) + EPS);
        B2 = __ldg(bet + d + 2) + (__ldg(bias + d + 2) - __ldg(mu + d + 2)) * A2;
        A3 = __ldg(gam + d + 3) * rsqrtf(__ldg(var + d + 3) + EPS);
        B3 = __ldg(bet + d + 3) + (__ldg(bias + d + 3) - __ldg(mu + d + 3)) * A3;
    }
    for (int w = gw; w < n; w += GW) {
        float di = g_dinv[w];
        int cnt = g_deg[w];
        const int* __restrict__ pl = g_perm + (size_t)w * SLOTS;
        float a0, a1, a2, a3;
        if (h == 0) {
            uint2 v = __ldg(fb + (size_t)w * 16 + li);
            float2 p0 = bf2f(v.x), p1 = bf2f(v.y);
            a0 = p0.x; a1 = p0.y; a2 = p1.x; a3 = p1.y;
        } else {
            a0 = 0.f; a1 = 0.f; a2 = 0.f; a3 = 0.f;
        }
        int e = h;
        for (; e + 6 < cnt; e += 8) {
            int s0 = __ldg(pl + e), s1 = __ldg(pl + e + 2);
            int s2 = __ldg(pl + e + 4), s3 = __ldg(pl + e + 6);
            uint2 v0 = __ldg(fb + (size_t)s0 * 16 + li);
            uint2 v1 = __ldg(fb + (size_t)s1 * 16 + li);
            uint2 v2 = __ldg(fb + (size_t)s2 * 16 + li);
            uint2 v3 = __ldg(fb + (size_t)s3 * 16 + li);
            float2 p;
            p = bf2f(v0.x); a0 += p.x; a1 += p.y;  p = bf2f(v0.y); a2 += p.x; a3 += p.y;
            p = bf2f(v1.x); a0 += p.x; a1 += p.y;  p = bf2f(v1.y); a2 += p.x; a3 += p.y;
            p = bf2f(v2.x); a0 += p.x; a1 += p.y;  p = bf2f(v2.y); a2 += p.x; a3 += p.y;
            p = bf2f(v3.x); a0 += p.x; a1 += p.y;  p = bf2f(v3.y); a2 += p.x; a3 += p.y;
        }
        for (; e < cnt; e += 2) {
            int sn = __ldg(pl + e);
            uint2 v = __ldg(fb + (size_t)sn * 16 + li);
            float2 p0 = bf2f(v.x), p1 = bf2f(v.y);
            a0 += p0.x; a1 += p0.y; a2 += p1.x; a3 += p1.y;
        }
        __syncwarp();
        a0 += __shfl_down_sync(0xffffffffu, a0, 16);
        a1 += __shfl_down_sync(0xffffffffu, a1, 16);
        a2 += __shfl_down_sync(0xffffffffu, a2, 16);
        a3 += __shfl_down_sync(0xffffffffu, a3, 16);
        if (lane < 16) {
            float o0, o1, o2, o3;
            if constexpr (EPIL) {
                o0 = fmaxf(a0 * (di * A0) + B0, 0.f);
                o1 = fmaxf(a1 * (di * A1) + B1, 0.f);
                o2 = fmaxf(a2 * (di * A2) + B2, 0.f);
                o3 = fmaxf(a3 * (di * A3) + B3, 0.f);
            } else {
                o0 = a0 * di; o1 = a1 * di; o2 = a2 * di; o3 = a3 * di;
            }
            ob[(size_t)w * 16 + li] = make_uint2(f2bf(o0, o1), f2bf(o2, o3));
        }
    }
}

// ---------------- GCN agg (D=32), PRESCALED, two nodes per warp, bf16 out + BN epilogue ----------------
__device__ void stage_agg32_dual(const unsigned* __restrict__ featb, unsigned* __restrict__ outb, int n,
                                 int lane, int gw, int GW,
                                 const float* __restrict__ bias, const float* __restrict__ gam,
                                 const float* __restrict__ bet, const float* __restrict__ mu,
                                 const float* __restrict__ var) {
    int sub = lane >> 4;
    int li = lane & 15;
    int d0 = 2 * li, d1 = 2 * li + 1;
    float A0 = __ldg(gam + d0) * rsqrtf(__ldg(var + d0) + EPS);
    float B0 = __ldg(bet + d0) + (__ldg(bias + d0) - __ldg(mu + d0)) * A0;
    float A1 = __ldg(gam + d1) * rsqrtf(__ldg(var + d1) + EPS);
    float B1 = __ldg(bet + d1) + (__ldg(bias + d1) - __ldg(mu + d1)) * A1;

    for (int base = gw * 2; base < n; base += GW * 2) {
        int w = base + sub;
        bool valid = w < n;
        int wc = valid ? w : n - 1;
        float di = g_dinv[wc];
        int cnt = g_deg[wc];
        int cnto = __shfl_xor_sync(0xffffffffu, cnt, 16);
        int cmax = cnt > cnto ? cnt : cnto;
        const int* __restrict__ pl = g_perm + (size_t)wc * SLOTS;
        float ax, ay;
        {
            float2 v = bf2f(__ldg(featb + (size_t)wc * 16 + li));
            ax = v.x; ay = v.y;
        }
        int e = 0;
        for (; e + 4 <= cmax; e += 4) {
            int s[4]; float g[4]; unsigned r[4];
#pragma unroll
            for (int u = 0; u < 4; u++) {
                bool a = (e + u) < cnt;
                s[u] = a ? __ldg(pl + e + u) : wc;
                g[u] = a ? 1.f : 0.f;
            }
#pragma unroll
            for (int u = 0; u < 4; u++) r[u] = __ldg(featb + (size_t)s[u] * 16 + li);
#pragma unroll
            for (int u = 0; u < 4; u++) {
                float2 v = bf2f(r[u]);
                ax += g[u] * v.x; ay += g[u] * v.y;
            }
        }
        for (; e < cmax; e++) {
            bool a = e < cnt;
            int sn = a ? __ldg(pl + e) : wc;
            float g = a ? 1.f : 0.f;
            float2 v = bf2f(__ldg(featb + (size_t)sn * 16 + li));
            ax += g * v.x; ay += g * v.y;
        }
        ax = fmaxf(ax * (di * A0) + B0, 0.f);
        ay = fmaxf(ay * (di * A1) + B1, 0.f);
        if (valid) outb[(size_t)w * 16 + li] = f2bf(ax, ay);
    }
}

// ---------------- the megakernel ----------------
__global__ void __launch_bounds__(NTHR, 4)
k_mega(const float* __restrict__ x, const int* __restrict__ src, const int* __restrict__ dst,
       const int* __restrict__ batch, int n, int E, int G,
       const float* W1, const float* b1, const float* g1, const float* be1, const float* m1, const float* v1,
       const float* W2, const float* b2, const float* g2, const float* be2, const float* m2, const float* v2,
       const float* W3, const float* b3, const float* g3, const float* be3, const float* m3, const float* v3,
       const float* Wg, const float* ags, const float* agd, const float* bg,
       const float* Wc1, const float* bc1, const float* Wc2, const float* bc2,
       float* __restrict__ out) {
    int tid = threadIdx.x;
    int lane = tid & 31;
    int gt = blockIdx.x * NTHR + tid;
    int gw = gt >> 5;
    const int GT = NBLK * NTHR;
    const int GW = GT / 32;

    // S0: zero cursors/pool/cnt/gmax
    for (int i = gt; i < n; i += GT) g_cursor[i] = 0;
    if (gt < GMAX * 32) g_pool[gt] = 0.f;
    if (gt < GMAX) g_cnt[gt] = 0.f;
    if (gt < 4) g_gmaxu[gt] = 0u;
    gridbar();

    // S1: bucket scatter by dst
    for (int e = gt; e < E; e += GT) {
        int d = dst[e];
        int slot = atomicAdd(&g_cursor[d], 1);
        if (slot < SLOTS) g_perm[(size_t)d * SLOTS + slot] = src[e];
    }
    gridbar();

    // S2: finalize degree/dinv + convert x -> prescaled bf16 + graph node counts
    for (int i = gt; i < n; i += GT) {
        int c = g_cursor[i];
        if (c > SLOTS) c = SLOTS;
        g_deg[i] = c;
        g_dinv[i] = rsqrtf((float)(c + 1));
        atomicAdd(&g_cnt[__ldg(batch + i)], 1.f);
    }
    for (int i = gt; i < n * 32; i += GT) {
        int node = i >> 5;
        int c = g_cursor[node];
        if (c > SLOTS) c = SLOTS;
        float di = rsqrtf((float)(c + 1));
        g_B64a[i] = f2bf(di * __ldg(x + 2 * i), di * __ldg(x + 2 * i + 1));
    }
    gridbar();

    // S3: aggregate prescaled input (linearity), out = bf16(di*acc)
    stage_agg64<false>(g_B64a, g_B64b, n, lane, gw, GW, nullptr, nullptr, nullptr, nullptr, nullptr);
    gridbar();

    // S4: tf32 GEMM 64->128 + bias/BN/relu
    stage_mma<64, 128, 1, false, false>(g_B64b, g_B128, W1, n, lane, gw, GW, b1, g1, be1, m1, v1);
    gridbar();

    // S5: tf32 GEMM 128->64, out prescaled by dinv
    stage_mma<128, 64, 0, true, false>(g_B128, g_B64a, W2, n, lane, gw, GW, nullptr, nullptr, nullptr, nullptr, nullptr);
    gridbar();

    // S6: aggregate + bias/BN/relu (di folded into epilogue)
    stage_agg64<true>(g_B64a, g_B64b, n, lane, gw, GW, b2, g2, be2, m2, v2);
    gridbar();

    // S7: tf32 GEMM 64->32, out prescaled by dinv
    stage_mma<64, 32, 0, true, false>(g_B64b, g_B64a, W3, n, lane, gw, GW, nullptr, nullptr, nullptr, nullptr, nullptr);
    gridbar();

    // S8: aggregate + bias/BN/relu (32-dim) -> h3 in g_B64b
    stage_agg32_dual(g_B64a, g_B64b, n, lane, gw, GW, b3, g3, be3, m3, v3);
    gridbar();

    // S10: attention coefficients DIRECTLY from h3 via vs = Wg_h @ ags_h (no hh!)
    {
        unsigned* gm = reinterpret_cast<unsigned*>(smw);
        if (tid < 4) gm[tid] = 0u;
        // vs at smw[16..143], vd at smw[144..271]
        for (int t = tid; t < 128; t += NTHR) {
            int h = t >> 5, k = t & 31;
            float s = 0.f, d = 0.f;
            const float* wrow = Wg + k * 128 + h * 32;
#pragma unroll 8
            for (int j = 0; j < 32; j++) {
                float wv = __ldg(wrow + j);
                s += wv * __ldg(ags + h * 32 + j);
                d += wv * __ldg(agd + h * 32 + j);
            }
            smw[16 + t] = s;
            smw[144 + t] = d;
        }
        __syncthreads();
        int sub = lane >> 4, li = lane & 15;
        float m0 = -CUDART_INF_F, m1_ = -CUDART_INF_F, m2_ = -CUDART_INF_F, m3_ = -CUDART_INF_F;
        for (int base = gw * 2; base < n; base += GW * 2) {
            int node = base + sub;
            bool valid = node < n;
            int nc = valid ? node : n - 1;
            float2 p = bf2f(__ldg(g_B64b + (size_t)nc * 16 + li));
            float s0 = p.x * smw[16 + 2 * li]       + p.y * smw[16 + 2 * li + 1];
            float s1 = p.x * smw[16 + 32 + 2 * li]  + p.y * smw[16 + 32 + 2 * li + 1];
            float s2 = p.x * smw[16 + 64 + 2 * li]  + p.y * smw[16 + 64 + 2 * li + 1];
            float s3 = p.x * smw[16 + 96 + 2 * li]  + p.y * smw[16 + 96 + 2 * li + 1];
            float d0 = p.x * smw[144 + 2 * li]      + p.y * smw[144 + 2 * li + 1];
            float d1 = p.x * smw[144 + 32 + 2 * li] + p.y * smw[144 + 32 + 2 * li + 1];
            float d2 = p.x * smw[144 + 64 + 2 * li] + p.y * smw[144 + 64 + 2 * li + 1];
            float d3 = p.x * smw[144 + 96 + 2 * li] + p.y * smw[144 + 96 + 2 * li + 1];
#pragma unroll
            for (int off = 8; off; off >>= 1) {
                s0 += __shfl_xor_sync(0xffffffffu, s0, off);
                s1 += __shfl_xor_sync(0xffffffffu, s1, off);
                s2 += __shfl_xor_sync(0xffffffffu, s2, off);
                s3 += __shfl_xor_sync(0xffffffffu, s3, off);
                d0 += __shfl_xor_sync(0xffffffffu, d0, off);
                d1 += __shfl_xor_sync(0xffffffffu, d1, off);
                d2 += __shfl_xor_sync(0xffffffffu, d2, off);
                d3 += __shfl_xor_sync(0xffffffffu, d3, off);
            }
            if (li == 0 && valid) {
                *reinterpret_cast<float4*>(g_as + node * 4) = make_float4(s0, s1, s2, s3);
                *reinterpret_cast<float4*>(g_ad + node * 4) = make_float4(d0, d1, d2, d3);
                m0 = fmaxf(m0, s0); m1_ = fmaxf(m1_, s1);
                m2_ = fmaxf(m2_, s2); m3_ = fmaxf(m3_, s3);
            }
        }
        if ((lane & 15) == 0) {
            atomicMax(&gm[0], fenc(m0));
            atomicMax(&gm[1], fenc(m1_));
            atomicMax(&gm[2], fenc(m2_));
            atomicMax(&gm[3], fenc(m3_));
        }
        __syncthreads();
        if (tid < 4) atomicMax(&g_gmaxu[tid], gm[tid]);
    }
    gridbar();

    // S11: GAT gather on h3 (64B rows!): P[n, h*32+k] = (1/den) * sum_s att_sh * h3[s,k]
    {
        const uint2* h3r = reinterpret_cast<const uint2*>(g_B64b);   // 8 uint2 per row
        int myh = lane >> 3;     // head
        int li = lane & 7;       // uint2 idx -> dims [4li, 4li+4)
        float gmax = fdec(g_gmaxu[myh]);
        for (int nId = gw; nId < n; nId += GW) {
            const int* __restrict__ pl = g_perm + (size_t)nId * SLOTS;
            int cnt = g_deg[nId];
            float4 adn4 = __ldg(reinterpret_cast<const float4*>(g_ad) + nId);
            float adn = (myh == 0) ? adn4.x : (myh == 1) ? adn4.y : (myh == 2) ? adn4.z : adn4.w;
            float mx = lrelu(gmax + adn);

            float a0 = 0.f, a1 = 0.f, a2 = 0.f, a3 = 0.f;
            float den = 0.f;
            int e = 0;
            for (; e + 4 <= cnt; e += 4) {
                int s0 = __ldg(pl + e + 0), s1 = __ldg(pl + e + 1);
                int s2 = __ldg(pl + e + 2), s3 = __ldg(pl + e + 3);
                uint2 r0 = __ldg(h3r + (size_t)s0 * 8 + li);
                uint2 r1 = __ldg(h3r + (size_t)s1 * 8 + li);
                uint2 r2 = __ldg(h3r + (size_t)s2 * 8 + li);
                uint2 r3 = __ldg(h3r + (size_t)s3 * 8 + li);
                float w0 = __expf(lrelu(__ldg(&g_as[s0 * 4 + myh]) + adn) - mx);
                float w1 = __expf(lrelu(__ldg(&g_as[s1 * 4 + myh]) + adn) - mx);
                float w2 = __expf(lrelu(__ldg(&g_as[s2 * 4 + myh]) + adn) - mx);
                float w3 = __expf(lrelu(__ldg(&g_as[s3 * 4 + myh]) + adn) - mx);
                den += (w0 + w1) + (w2 + w3);
                float2 p, q;
                p = bf2f(r0.x); q = bf2f(r0.y);
                a0 += w0 * p.x; a1 += w0 * p.y; a2 += w0 * q.x; a3 += w0 * q.y;
                p = bf2f(r1.x); q = bf2f(r1.y);
                a0 += w1 * p.x; a1 += w1 * p.y; a2 += w1 * q.x; a3 += w1 * q.y;
                p = bf2f(r2.x); q = bf2f(r2.y);
                a0 += w2 * p.x; a1 += w2 * p.y; a2 += w2 * q.x; a3 += w2 * q.y;
                p = bf2f(r3.x); q = bf2f(r3.y);
                a0 += w3 * p.x; a1 += w3 * p.y; a2 += w3 * q.x; a3 += w3 * q.y;
            }
            for (; e <= cnt; e++) {
                int sn = (e < cnt) ? __ldg(pl + e) : nId;
                uint2 r = __ldg(h3r + (size_t)sn * 8 + li);
                float w = __expf(lrelu(__ldg(&g_as[sn * 4 + myh]) + adn) - mx);
                den += w;
                float2 p = bf2f(r.x), q = bf2f(r.y);
                a0 += w * p.x; a1 += w * p.y; a2 += w * q.x; a3 += w * q.y;
            }
            float inv = 1.f / den;
            // P row: lane covers cols [4*lane, 4*lane+4) -> uint2 at offset 2*lane
            *reinterpret_cast<uint2*>(g_B128 + (size_t)nId * 64 + 2 * lane) =
                make_uint2(f2bf(a0 * inv, a1 * inv), f2bf(a2 * inv, a3 * inv));
        }
    }
    gridbar();

    // S11b: GAT output GEMM: out32 = relu(P @ Wbig + bg), Wbig = head-stacked Wg * 0.25
    stage_mma<128, 32, 2, false, true>(g_B128, g_B64a, Wg, n, lane, gw, GW, bg, nullptr, nullptr, nullptr, nullptr);
    gridbar();

    // S12: pool accumulation
    for (int i = gt; i < n * 16; i += GT) {
        int node = i >> 4, li = i & 15;
        float2 v = bf2f(__ldg(g_B64a + (size_t)node * 16 + li));
        int b = __ldg(batch + node);
        atomicAdd(&g_pool[b * 32 + 2 * li], v.x);
        atomicAdd(&g_pool[b * 32 + 2 * li + 1], v.y);
    }
    gridbar();

    // S13: classifier head (block 0 only)
    if (blockIdx.x == 0) {
        float* pooled = smw;
        float* hid = smw + GMAX * 32;
        for (int t = tid; t < G * 32; t += NTHR) pooled[t] = g_pool[t] / fmaxf(g_cnt[t >> 5], 1.f);
        __syncthreads();
        for (int t = tid; t < G * 16; t += NTHR) {
            int g = t >> 4, j = t & 15;
            float s = __ldg(bc1 + j);
            for (int k = 0; k < 32; k++) s += pooled[g * 32 + k] * __ldg(Wc1 + k * 16 + j);
            hid[t] = fmaxf(s, 0.f);
        }
        __syncthreads();
        for (int t = tid; t < G * 5; t += NTHR) {
            int g = t / 5, c = t % 5;
            float s = __ldg(bc2 + c);
            for (int k = 0; k < 16; k++) s += hid[g * 16 + k] * __ldg(Wc2 + k * 5 + c);
            out[t] = s;
        }
    }
}

// ---------------- host ----------------
extern "C" void kernel_launch(void* const* d_in, const int* in_sizes, int n_in,
                              void* d_out, int out_size) {
    const float* x = (const float*)d_in[0];
    const int* ei = (const int*)d_in[1];
    const int* batch = (const int*)d_in[2];
    int n = in_sizes[0] / 64;
    int E = in_sizes[1] / 2;
    int G = out_size / 5;

    const float *W1, *b1, *W2, *b2, *W3, *b3;
    const float *g1, *be1, *m1, *v1, *g2, *be2, *m2, *v2, *g3, *be3, *m3, *v3;
    const float *Wg, *ags, *agd, *bg, *Wc1, *bc1, *Wc2, *bc2;

    if (in_sizes[5] == 128 * 64) {
        W1 = (const float*)d_in[3];  b1 = (const float*)d_in[4];
        W2 = (const float*)d_in[5];  b2 = (const float*)d_in[6];
        W3 = (const float*)d_in[7];  b3 = (const float*)d_in[8];
        g1 = (const float*)d_in[9];  be1 = (const float*)d_in[10];
        m1 = (const float*)d_in[11]; v1 = (const float*)d_in[12];
        g2 = (const float*)d_in[13]; be2 = (const float*)d_in[14];
        m2 = (const float*)d_in[15]; v2 = (const float*)d_in[16];
        g3 = (const float*)d_in[17]; be3 = (const float*)d_in[18];
        m3 = (const float*)d_in[19]; v3 = (const float*)d_in[20];
        Wg = (const float*)d_in[21]; ags = (const float*)d_in[22];
        agd = (const float*)d_in[23]; bg = (const float*)d_in[24];
        Wc1 = (const float*)d_in[25]; bc1 = (const float*)d_in[26];
        Wc2 = (const float*)d_in[27]; bc2 = (const float*)d_in[28];
    } else {
        W1 = (const float*)d_in[3];  b1 = (const float*)d_in[4];
        g1 = (const float*)d_in[5];  be1 = (const float*)d_in[6];
        m1 = (const float*)d_in[7];  v1 = (const float*)d_in[8];
        W2 = (const float*)d_in[9];  b2 = (const float*)d_in[10];
        g2 = (const float*)d_in[11]; be2 = (const float*)d_in[12];
        m2 = (const float*)d_in[13]; v2 = (const float*)d_in[14];
        W3 = (const float*)d_in[15]; b3 = (const float*)d_in[16];
        g3 = (const float*)d_in[17]; be3 = (const float*)d_in[18];
        m3 = (const float*)d_in[19]; v3 = (const float*)d_in[20];
        Wg = (const float*)d_in[21]; ags = (const float*)d_in[22];
        agd = (const float*)d_in[23]; bg = (const float*)d_in[24];
        Wc1 = (const float*)d_in[25]; bc1 = (const float*)d_in[26];
        Wc2 = (const float*)d_in[27]; bc2 = (const float*)d_in[28];
    }

    const int* src = ei;
    const int* dst = ei + E;

    k_mega<<<NBLK, NTHR>>>(x, src, dst, batch, n, E, G,
                           W1, b1, g1, be1, m1, v1,
                           W2, b2, g2, be2, m2, v2,
                           W3, b3, g3, be3, m3, v3,
                           Wg, ags, agd, bg,
                           Wc1, bc1, Wc2, bc2,
                           (float*)d_out);
}